// round 2
// baseline (speedup 1.0000x reference)
#include <cuda_runtime.h>

#define Sdim 2048
#define Edim 256
#define NBATCH 16
#define BM 128
#define BN 64
#define SK 260          // 256 + 4-float pad: keeps float4 alignment, breaks worst bank conflicts
#define NTHREADS 256

#define SMEM_FLOATS (BM*SK + BN*SK + BM*17 + BM)
#define SMEM_BYTES  (SMEM_FLOATS * 4)

typedef unsigned long long u64t;

__device__ float g_sq[NBATCH * Sdim];

// Packed f32x2 FMA: d(.lo,.hi) += a(.lo,.hi) * b(.lo,.hi). sm_103a-only pipe, PTX-only.
__device__ __forceinline__ void fma2(u64t& d, u64t a, u64t b) {
    asm("fma.rn.f32x2 %0, %1, %2, %0;" : "+l"(d) : "l"(a), "l"(b));
}

// Kernel 0: per-row squared norms. One warp per row.
__global__ __launch_bounds__(NTHREADS) void sqnorm_kernel(const float* __restrict__ x) {
    int row  = blockIdx.x * 8 + (threadIdx.x >> 5);
    int lane = threadIdx.x & 31;
    const float4* xr = reinterpret_cast<const float4*>(x + (size_t)row * Edim);
    float4 v0 = xr[lane], v1 = xr[lane + 32];
    float s = v0.x*v0.x + v0.y*v0.y + v0.z*v0.z + v0.w*v0.w
            + v1.x*v1.x + v1.y*v1.y + v1.z*v1.z + v1.w*v1.w;
    #pragma unroll
    for (int o = 16; o; o >>= 1) s += __shfl_xor_sync(0xffffffffu, s, o);
    if (lane == 0) g_sq[row] = s;
}

// Kernel 1: fused gram + exp + deterministic row-sum + rescale.
// Grid: (Sdim/BM row tiles, NBATCH). One CTA owns 128 full output rows.
__global__ __launch_bounds__(NTHREADS) void simgram_kernel(const float* __restrict__ x,
                                                           float* __restrict__ out) {
    extern __shared__ float sm[];
    float* As   = sm;                  // [BM][SK]  (row-major, k contiguous)
    float* Bs   = sm + BM * SK;        // [BN][SK]
    float* sums = Bs + BN * SK;        // [BM][17]
    float* inv  = sums + BM * 17;      // [BM]

    const int tid = threadIdx.x;
    const int tx  = tid & 15;          // column group: j = tx + 16*n
    const int ty  = tid >> 4;          // row group:    i = ty*8 + m
    const int b   = blockIdx.y;
    const int i0  = blockIdx.x * BM;

    const float* xb  = x   + (size_t)b * Sdim * Edim;
    float*       outb = out + (size_t)b * Sdim * Sdim;

    // ---- Load A tile (128 x 256), coalesced LDG.128, conflict-free STS.128 ----
    {
        const int kv = tid & 63;       // float4 index along k
        const int ib = tid >> 6;       // 4 rows per pass of 256 threads
        #pragma unroll 4
        for (int it = 0; it < BM / 4; ++it) {
            int i = ib + 4 * it;
            float4 v = *reinterpret_cast<const float4*>(xb + (size_t)(i0 + i) * Edim + 4 * kv);
            *reinterpret_cast<float4*>(As + i * SK + 4 * kv) = v;
        }
    }

    float sqi[8];
    #pragma unroll
    for (int m = 0; m < 8; ++m) sqi[m] = g_sq[b * Sdim + i0 + ty * 8 + m];

    float rsum[8];
    #pragma unroll
    for (int m = 0; m < 8; ++m) rsum[m] = 0.f;

    for (int jc = 0; jc < Sdim / BN; ++jc) {
        const int j0 = jc * BN;
        __syncthreads();               // previous chunk done reading Bs
        // ---- Load B tile (64 x 256) ----
        {
            const int kv = tid & 63;
            const int jb = tid >> 6;
            #pragma unroll 4
            for (int it = 0; it < BN / 4; ++it) {
                int j = jb + 4 * it;
                float4 v = *reinterpret_cast<const float4*>(xb + (size_t)(j0 + j) * Edim + 4 * kv);
                *reinterpret_cast<float4*>(Bs + j * SK + 4 * kv) = v;
            }
        }
        __syncthreads();

        // ---- 128x64x256 register-tiled GEMM on the f32x2 pipe ----
        u64t acc[8][4];
        #pragma unroll
        for (int m = 0; m < 8; ++m)
            #pragma unroll
            for (int n = 0; n < 4; ++n) acc[m][n] = 0ull;

        #pragma unroll 4
        for (int k4 = 0; k4 < Edim / 4; ++k4) {
            ulonglong2 bb[4];
            #pragma unroll
            for (int n = 0; n < 4; ++n)
                bb[n] = *reinterpret_cast<const ulonglong2*>(Bs + (tx + 16 * n) * SK + 4 * k4);
            #pragma unroll
            for (int m = 0; m < 8; ++m) {
                ulonglong2 aa = *reinterpret_cast<const ulonglong2*>(As + (ty * 8 + m) * SK + 4 * k4);
                #pragma unroll
                for (int n = 0; n < 4; ++n) {
                    fma2(acc[m][n], aa.x, bb[n].x);   // k, k+1
                    fma2(acc[m][n], aa.y, bb[n].y);   // k+2, k+3
                }
            }
        }

        // ---- Fused epilogue: logits are <= 0 with max exactly 0 -> no max pass ----
        #pragma unroll
        for (int n = 0; n < 4; ++n) {
            int j = j0 + tx + 16 * n;
            float sqj = g_sq[b * Sdim + j];
            #pragma unroll
            for (int m = 0; m < 8; ++m) {
                float2 dv = *reinterpret_cast<float2*>(&acc[m][n]);
                float dot = dv.x + dv.y;
                // logit = (2*dot - sqi - sqj) / 16
                float p = __expf(fmaf(dot, 0.125f, -0.0625f * (sqi[m] + sqj)));
                rsum[m] += p;
                outb[(size_t)(i0 + ty * 8 + m) * Sdim + j] = p;   // unnormalized
            }
        }
    }

    // ---- Deterministic row-sum reduction (no FP atomics) ----
    #pragma unroll
    for (int m = 0; m < 8; ++m) sums[(ty * 8 + m) * 17 + tx] = rsum[m];
    __syncthreads();
    if (tid < BM) {
        float t = 0.f;
        #pragma unroll
        for (int q = 0; q < 16; ++q) t += sums[tid * 17 + q];
        inv[tid] = 1.0f / t;
    }
    __syncthreads();

    // ---- Rescale pass over the (L2-resident) 128x2048 tile just written ----
    #pragma unroll 2
    for (int r = 0; r < BM; ++r) {
        float s = inv[r];
        float4* row = reinterpret_cast<float4*>(outb + (size_t)(i0 + r) * Sdim);
        float4 v0 = row[tid];
        float4 v1 = row[tid + 256];
        v0.x *= s; v0.y *= s; v0.z *= s; v0.w *= s;
        v1.x *= s; v1.y *= s; v1.z *= s; v1.w *= s;
        row[tid]       = v0;
        row[tid + 256] = v1;
    }
}

extern "C" void kernel_launch(void* const* d_in, const int* in_sizes, int n_in,
                              void* d_out, int out_size) {
    const float* x  = (const float*)d_in[0];
    float*       out = (float*)d_out;

    cudaFuncSetAttribute(simgram_kernel,
                         cudaFuncAttributeMaxDynamicSharedMemorySize, SMEM_BYTES);

    sqnorm_kernel<<<NBATCH * Sdim / 8, NTHREADS>>>(x);
    simgram_kernel<<<dim3(Sdim / BM, NBATCH), NTHREADS, SMEM_BYTES>>>(x, out);
}

// round 4
// speedup vs baseline: 2.4693x; 2.4693x over previous
#include <cuda_runtime.h>
#include <cuda_bf16.h>
#include <cstdint>

#define Sdim   2048
#define Edim   256
#define KDIM   768                 // [hi | lo | hi] · [hi | hi | lo]
#define NBATCH 16
#define BM     128
#define BN     128
#define BK     32
#define NITER  (KDIM / BK)         // 24
#define NPART  (Sdim / BN)         // 16
#define ROWSTRIDE 80               // bytes per BK-row in smem: (5r+c)%8 distinct -> conflict-free ldmatrix
#define ASTAGE_BYTES (BM * ROWSTRIDE)
#define STAGE_BYTES  (2 * BM * ROWSTRIDE)   // A + B = 20480
#define NSTAGE 3
#define SMEM_GEMM (NSTAGE * STAGE_BYTES)    // 61440

__device__ __nv_bfloat16 g_a[(size_t)NBATCH * Sdim * KDIM];
__device__ __nv_bfloat16 g_b[(size_t)NBATCH * Sdim * KDIM];
__device__ float         g_sq[NBATCH * Sdim];
__device__ float         g_part[(size_t)NBATCH * Sdim * NPART];

__device__ __forceinline__ uint32_t smem_to_u32(const void* p) {
    uint32_t a;
    asm("{ .reg .u64 t; cvta.to.shared.u64 t, %1; cvt.u32.u64 %0, t; }" : "=r"(a) : "l"(p));
    return a;
}

#define CP16(dst, src) \
    asm volatile("cp.async.cg.shared.global [%0], [%1], 16;" :: "r"(dst), "l"(src) : "memory")
#define CP_COMMIT() asm volatile("cp.async.commit_group;" ::: "memory")

__device__ __forceinline__ void ldmx4(uint32_t* r, uint32_t addr) {
    asm volatile("ldmatrix.sync.aligned.m8n8.x4.shared.b16 {%0,%1,%2,%3}, [%4];"
                 : "=r"(r[0]), "=r"(r[1]), "=r"(r[2]), "=r"(r[3]) : "r"(addr));
}
__device__ __forceinline__ void mma16816(float* d, const uint32_t* a, const uint32_t* b) {
    asm volatile("mma.sync.aligned.m16n8k16.row.col.f32.bf16.bf16.f32 "
                 "{%0,%1,%2,%3}, {%4,%5,%6,%7}, {%8,%9}, {%0,%1,%2,%3};"
                 : "+f"(d[0]), "+f"(d[1]), "+f"(d[2]), "+f"(d[3])
                 : "r"(a[0]), "r"(a[1]), "r"(a[2]), "r"(a[3]), "r"(b[0]), "r"(b[1]));
}

// ================= Kernel 1: bf16 hi/lo split + sq norms =================
// One warp per row. A' = [hi|lo|hi], B' = [hi|hi|lo].
__global__ __launch_bounds__(256) void split_kernel(const float* __restrict__ x) {
    int row  = blockIdx.x * 8 + (threadIdx.x >> 5);
    int lane = threadIdx.x & 31;
    const float4* xr = reinterpret_cast<const float4*>(x + (size_t)row * Edim);
    float4 v0 = xr[lane], v1 = xr[lane + 32];
    float vv[8] = {v0.x, v0.y, v0.z, v0.w, v1.x, v1.y, v1.z, v1.w};

    float s = 0.f;
    uint32_t ph[4], pl[4];
    #pragma unroll
    for (int q = 0; q < 4; ++q) {
        __nv_bfloat16 h0 = __float2bfloat16(vv[2*q]),   h1 = __float2bfloat16(vv[2*q+1]);
        __nv_bfloat16 l0 = __float2bfloat16(vv[2*q]   - __bfloat162float(h0));
        __nv_bfloat16 l1 = __float2bfloat16(vv[2*q+1] - __bfloat162float(h1));
        __nv_bfloat162 hp = __halves2bfloat162(h0, h1), lp = __halves2bfloat162(l0, l1);
        ph[q] = *reinterpret_cast<uint32_t*>(&hp);
        pl[q] = *reinterpret_cast<uint32_t*>(&lp);
        s += vv[2*q]*vv[2*q] + vv[2*q+1]*vv[2*q+1];
    }
    uint2 hi0 = make_uint2(ph[0], ph[1]), hi1 = make_uint2(ph[2], ph[3]);
    uint2 lo0 = make_uint2(pl[0], pl[1]), lo1 = make_uint2(pl[2], pl[3]);

    __nv_bfloat16* A = g_a + (size_t)row * KDIM;   // cols 4*lane and 128+4*lane per region
    __nv_bfloat16* B = g_b + (size_t)row * KDIM;
    int c = 4 * lane;
    *reinterpret_cast<uint2*>(A +       c) = hi0;  *reinterpret_cast<uint2*>(A + 128 + c) = hi1;
    *reinterpret_cast<uint2*>(A + 256 + c) = lo0;  *reinterpret_cast<uint2*>(A + 384 + c) = lo1;
    *reinterpret_cast<uint2*>(A + 512 + c) = hi0;  *reinterpret_cast<uint2*>(A + 640 + c) = hi1;
    *reinterpret_cast<uint2*>(B +       c) = hi0;  *reinterpret_cast<uint2*>(B + 128 + c) = hi1;
    *reinterpret_cast<uint2*>(B + 256 + c) = hi0;  *reinterpret_cast<uint2*>(B + 384 + c) = hi1;
    *reinterpret_cast<uint2*>(B + 512 + c) = lo0;  *reinterpret_cast<uint2*>(B + 640 + c) = lo1;

    #pragma unroll
    for (int o = 16; o; o >>= 1) s += __shfl_xor_sync(0xffffffffu, s, o);
    if (lane == 0) g_sq[row] = s;
}

// ================= Kernel 2: HMMA gram + exp + row partials =================
__global__ __launch_bounds__(256) void gemm_kernel(float* __restrict__ out) {
    extern __shared__ char smem[];
    uint32_t sbase = smem_to_u32(smem);
    const int tid = threadIdx.x, l = tid & 31, wid = tid >> 5;
    const int warp_m = wid & 3, warp_n = wid >> 2;     // 4 x 2 warps, 32x64 tiles
    const int b = blockIdx.z, by = blockIdx.y, bx = blockIdx.x;

    const __nv_bfloat16* Ag = g_a + ((size_t)b * Sdim + by * BM) * KDIM;
    const __nv_bfloat16* Bg = g_b + ((size_t)b * Sdim + bx * BN) * KDIM;

    // cp.async mapping: 512 16B-chunks per operand tile, 2 per thread
    const int crow  = tid >> 1;
    const int ccol0 = (tid & 1) * 2;                   // chunks ccol0, ccol0+1
    const char* srcA = (const char*)(Ag + (size_t)crow * KDIM + ccol0 * 8);
    const char* srcB = (const char*)(Bg + (size_t)crow * KDIM + ccol0 * 8);
    const uint32_t dA = crow * ROWSTRIDE + ccol0 * 16;
    const uint32_t dB = dA + ASTAGE_BYTES;

    // ldmatrix per-thread offsets
    uint32_t aoff[2];
    #pragma unroll
    for (int m = 0; m < 2; ++m)
        aoff[m] = (warp_m * 32 + m * 16 + (l & 15)) * ROWSTRIDE + (l >> 4) * 16;
    uint32_t boff[4];
    {
        int grp = l >> 3, nof = (grp >> 1) * 8 + (l & 7), cof = (grp & 1) * 16;
        #pragma unroll
        for (int p = 0; p < 4; ++p)
            boff[p] = ASTAGE_BYTES + (warp_n * 64 + p * 16 + nof) * ROWSTRIDE + cof;
    }

    // prologue: stages 0,1
    #pragma unroll
    for (int it = 0; it < 2; ++it) {
        uint32_t so = sbase + it * STAGE_BYTES;
        const char* sa = srcA + it * 64;
        const char* sb = srcB + it * 64;
        CP16(so + dA, sa); CP16(so + dA + 16, sa + 16);
        CP16(so + dB, sb); CP16(so + dB + 16, sb + 16);
        CP_COMMIT();
    }

    float d[2][8][4];
    #pragma unroll
    for (int m = 0; m < 2; ++m)
        #pragma unroll
        for (int n = 0; n < 8; ++n)
            #pragma unroll
            for (int q = 0; q < 4; ++q) d[m][n][q] = 0.f;

    for (int it = 0; it < NITER; ++it) {
        if (it == NITER - 1) asm volatile("cp.async.wait_group 0;" ::: "memory");
        else                 asm volatile("cp.async.wait_group 1;" ::: "memory");
        __syncthreads();
        uint32_t sb = sbase + (it % 3) * STAGE_BYTES;
        #pragma unroll
        for (int ks = 0; ks < 2; ++ks) {
            uint32_t a[2][4], bb[8][2];
            #pragma unroll
            for (int m = 0; m < 2; ++m) ldmx4(a[m], sb + aoff[m] + ks * 32);
            #pragma unroll
            for (int p = 0; p < 4; ++p) {
                uint32_t r[4];
                ldmx4(r, sb + boff[p] + ks * 32);
                bb[2*p][0] = r[0]; bb[2*p][1] = r[1];
                bb[2*p+1][0] = r[2]; bb[2*p+1][1] = r[3];
            }
            #pragma unroll
            for (int m = 0; m < 2; ++m)
                #pragma unroll
                for (int n = 0; n < 8; ++n) mma16816(d[m][n], a[m], bb[n]);
        }
        if (it + 2 < NITER) {
            uint32_t so = sbase + ((it + 2) % 3) * STAGE_BYTES;
            const char* sa = srcA + (it + 2) * 64;
            const char* sb2 = srcB + (it + 2) * 64;
            CP16(so + dA, sa); CP16(so + dA + 16, sa + 16);
            CP16(so + dB, sb2); CP16(so + dB + 16, sb2 + 16);
            CP_COMMIT();
        }
    }

    // ---- epilogue: exp (logits <= 0, no max pass), direct stores, row partials ----
    __syncthreads();                       // smem reuse for partials
    float* spart = reinterpret_cast<float*>(smem);   // [128][2]

    float sqi[4];
    #pragma unroll
    for (int m = 0; m < 2; ++m)
        #pragma unroll
        for (int h = 0; h < 2; ++h)
            sqi[2*m+h] = g_sq[b * Sdim + by * BM + warp_m * 32 + m * 16 + h * 8 + (l >> 2)];
    float2 sqj[8];
    #pragma unroll
    for (int n = 0; n < 8; ++n)
        sqj[n] = *reinterpret_cast<const float2*>(
            &g_sq[b * Sdim + bx * BN + warp_n * 64 + n * 8 + 2 * (l & 3)]);

    float* ob = out + ((size_t)b * Sdim + by * BM) * Sdim + bx * BN;
    float rs[4] = {0.f, 0.f, 0.f, 0.f};
    #pragma unroll
    for (int m = 0; m < 2; ++m) {
        #pragma unroll
        for (int h = 0; h < 2; ++h) {
            int row = warp_m * 32 + m * 16 + h * 8 + (l >> 2);
            float bi = -0.0625f * sqi[2*m+h];
            float* orow = ob + (size_t)row * Sdim + warp_n * 64 + 2 * (l & 3);
            float acc = 0.f;
            #pragma unroll
            for (int n = 0; n < 8; ++n) {
                float p0 = __expf(fmaf(d[m][n][2*h],     0.125f, fmaf(sqj[n].x, -0.0625f, bi)));
                float p1 = __expf(fmaf(d[m][n][2*h + 1], 0.125f, fmaf(sqj[n].y, -0.0625f, bi)));
                acc += p0 + p1;
                *reinterpret_cast<float2*>(orow + n * 8) = make_float2(p0, p1);
            }
            rs[2*m+h] = acc;
        }
    }
    #pragma unroll
    for (int i = 0; i < 4; ++i) {
        rs[i] += __shfl_xor_sync(0xffffffffu, rs[i], 1);
        rs[i] += __shfl_xor_sync(0xffffffffu, rs[i], 2);
    }
    if ((l & 3) == 0) {
        #pragma unroll
        for (int m = 0; m < 2; ++m)
            #pragma unroll
            for (int h = 0; h < 2; ++h) {
                int row = warp_m * 32 + m * 16 + h * 8 + (l >> 2);
                spart[row * 2 + warp_n] = rs[2*m+h];
            }
    }
    __syncthreads();
    if (tid < BM) {
        float s = spart[tid * 2] + spart[tid * 2 + 1];
        g_part[((size_t)b * Sdim + by * BM + tid) * NPART + bx] = s;
    }
}

// ================= Kernel 3: normalize =================
__global__ __launch_bounds__(256) void norm_kernel(float* __restrict__ out) {
    int w = threadIdx.x >> 5, l = threadIdx.x & 31;
    size_t row = (size_t)blockIdx.x * 8 + w;          // over NBATCH*Sdim
    float v = (l < NPART) ? g_part[row * NPART + l] : 0.f;
    #pragma unroll
    for (int o = 16; o; o >>= 1) v += __shfl_xor_sync(0xffffffffu, v, o);
    float inv = 1.0f / v;
    float4* o4 = reinterpret_cast<float4*>(out + row * Sdim);
    #pragma unroll 4
    for (int k = 0; k < Sdim / 4 / 32; ++k) {
        float4 t = o4[l + 32 * k];
        t.x *= inv; t.y *= inv; t.z *= inv; t.w *= inv;
        o4[l + 32 * k] = t;
    }
}

extern "C" void kernel_launch(void* const* d_in, const int* in_sizes, int n_in,
                              void* d_out, int out_size) {
    const float* x  = (const float*)d_in[0];
    float*       out = (float*)d_out;

    cudaFuncSetAttribute(gemm_kernel, cudaFuncAttributeMaxDynamicSharedMemorySize, SMEM_GEMM);

    split_kernel<<<NBATCH * Sdim / 8, 256>>>(x);
    gemm_kernel<<<dim3(NPART, Sdim / BM, NBATCH), 256, SMEM_GEMM>>>(out);
    norm_kernel<<<NBATCH * Sdim / 8, 256>>>(out);
}

// round 5
// speedup vs baseline: 3.3352x; 1.3506x over previous
#include <cuda_runtime.h>
#include <cuda_bf16.h>
#include <cstdint>

#define Sdim   2048
#define Edim   256
#define KDIM   768                 // [hi | lo | hi] · [hi | hi | lo]
#define NBATCH 16
#define BM     128
#define BN     128
#define BK     32
#define NITER  (KDIM / BK)         // 24
#define NPART  (Sdim / BN)         // 16
#define NTRI   (NPART * (NPART + 1) / 2)    // 136 tile pairs per batch
#define ROWSTRIDE 80               // bytes per BK-row in smem: (5r+c)%8 distinct -> conflict-free ldmatrix
#define ASTAGE_BYTES (BM * ROWSTRIDE)
#define STAGE_BYTES  (2 * BM * ROWSTRIDE)   // A + B = 20480
#define NSTAGE 3
#define SMEM_MAIN (NSTAGE * STAGE_BYTES)    // 61440
#define TSTRIDE 132                          // transpose stage stride (floats): conflict-free
#define SMEM_EPI  (1024 + BM * TSTRIDE * 4)  // spart + stage = 68608
#define SMEM_DYN  (SMEM_EPI > SMEM_MAIN ? SMEM_EPI : SMEM_MAIN)

__device__ __nv_bfloat16 g_a[(size_t)NBATCH * Sdim * KDIM];
__device__ __nv_bfloat16 g_b[(size_t)NBATCH * Sdim * KDIM];
__device__ float         g_sq[NBATCH * Sdim];
__device__ float         g_part[(size_t)NBATCH * Sdim * NPART];

__device__ __forceinline__ uint32_t smem_to_u32(const void* p) {
    uint32_t a;
    asm("{ .reg .u64 t; cvta.to.shared.u64 t, %1; cvt.u32.u64 %0, t; }" : "=r"(a) : "l"(p));
    return a;
}

#define CP16(dst, src) \
    asm volatile("cp.async.cg.shared.global [%0], [%1], 16;" :: "r"(dst), "l"(src) : "memory")
#define CP_COMMIT() asm volatile("cp.async.commit_group;" ::: "memory")

__device__ __forceinline__ void ldmx4(uint32_t* r, uint32_t addr) {
    asm volatile("ldmatrix.sync.aligned.m8n8.x4.shared.b16 {%0,%1,%2,%3}, [%4];"
                 : "=r"(r[0]), "=r"(r[1]), "=r"(r[2]), "=r"(r[3]) : "r"(addr));
}
__device__ __forceinline__ void mma16816(float* d, const uint32_t* a, const uint32_t* b) {
    asm volatile("mma.sync.aligned.m16n8k16.row.col.f32.bf16.bf16.f32 "
                 "{%0,%1,%2,%3}, {%4,%5,%6,%7}, {%8,%9}, {%0,%1,%2,%3};"
                 : "+f"(d[0]), "+f"(d[1]), "+f"(d[2]), "+f"(d[3])
                 : "r"(a[0]), "r"(a[1]), "r"(a[2]), "r"(a[3]), "r"(b[0]), "r"(b[1]));
}

// ================= Kernel 1: bf16 hi/lo split + sq norms =================
__global__ __launch_bounds__(256) void split_kernel(const float* __restrict__ x) {
    int row  = blockIdx.x * 8 + (threadIdx.x >> 5);
    int lane = threadIdx.x & 31;
    const float4* xr = reinterpret_cast<const float4*>(x + (size_t)row * Edim);
    float4 v0 = xr[lane], v1 = xr[lane + 32];
    float vv[8] = {v0.x, v0.y, v0.z, v0.w, v1.x, v1.y, v1.z, v1.w};

    float s = 0.f;
    uint32_t ph[4], pl[4];
    #pragma unroll
    for (int q = 0; q < 4; ++q) {
        __nv_bfloat16 h0 = __float2bfloat16(vv[2*q]),   h1 = __float2bfloat16(vv[2*q+1]);
        __nv_bfloat16 l0 = __float2bfloat16(vv[2*q]   - __bfloat162float(h0));
        __nv_bfloat16 l1 = __float2bfloat16(vv[2*q+1] - __bfloat162float(h1));
        __nv_bfloat162 hp = __halves2bfloat162(h0, h1), lp = __halves2bfloat162(l0, l1);
        ph[q] = *reinterpret_cast<uint32_t*>(&hp);
        pl[q] = *reinterpret_cast<uint32_t*>(&lp);
        s += vv[2*q]*vv[2*q] + vv[2*q+1]*vv[2*q+1];
    }
    uint2 hi0 = make_uint2(ph[0], ph[1]), hi1 = make_uint2(ph[2], ph[3]);
    uint2 lo0 = make_uint2(pl[0], pl[1]), lo1 = make_uint2(pl[2], pl[3]);

    __nv_bfloat16* A = g_a + (size_t)row * KDIM;
    __nv_bfloat16* B = g_b + (size_t)row * KDIM;
    int c = 4 * lane;
    *reinterpret_cast<uint2*>(A +       c) = hi0;  *reinterpret_cast<uint2*>(A + 128 + c) = hi1;
    *reinterpret_cast<uint2*>(A + 256 + c) = lo0;  *reinterpret_cast<uint2*>(A + 384 + c) = lo1;
    *reinterpret_cast<uint2*>(A + 512 + c) = hi0;  *reinterpret_cast<uint2*>(A + 640 + c) = hi1;
    *reinterpret_cast<uint2*>(B +       c) = hi0;  *reinterpret_cast<uint2*>(B + 128 + c) = hi1;
    *reinterpret_cast<uint2*>(B + 256 + c) = hi0;  *reinterpret_cast<uint2*>(B + 384 + c) = hi1;
    *reinterpret_cast<uint2*>(B + 512 + c) = lo0;  *reinterpret_cast<uint2*>(B + 640 + c) = lo1;

    #pragma unroll
    for (int o = 16; o; o >>= 1) s += __shfl_xor_sync(0xffffffffu, s, o);
    if (lane == 0) g_sq[row] = s;
}

// ================= Kernel 2: HMMA gram + exp, upper-triangular tiles =================
__global__ __launch_bounds__(256) void gemm_kernel(float* __restrict__ out) {
    extern __shared__ char smem[];
    uint32_t sbase = smem_to_u32(smem);
    const int tid = threadIdx.x, l = tid & 31, wid = tid >> 5;
    const int warp_m = wid & 3, warp_n = wid >> 2;     // 4 x 2 warps, 32x64 tiles
    const int b = blockIdx.z;

    // triangular decode: tile pair (by, bx) with bx >= by
    int by = 0, rem = blockIdx.x;
    while (rem >= NPART - by) { rem -= NPART - by; ++by; }
    const int bx = by + rem;
    const bool offdiag = (bx != by);

    const __nv_bfloat16* Ag = g_a + ((size_t)b * Sdim + by * BM) * KDIM;
    const __nv_bfloat16* Bg = g_b + ((size_t)b * Sdim + bx * BN) * KDIM;

    const int crow  = tid >> 1;
    const int ccol0 = (tid & 1) * 2;
    const char* srcA = (const char*)(Ag + (size_t)crow * KDIM + ccol0 * 8);
    const char* srcB = (const char*)(Bg + (size_t)crow * KDIM + ccol0 * 8);
    const uint32_t dA = crow * ROWSTRIDE + ccol0 * 16;
    const uint32_t dB = dA + ASTAGE_BYTES;

    uint32_t aoff[2];
    #pragma unroll
    for (int m = 0; m < 2; ++m)
        aoff[m] = (warp_m * 32 + m * 16 + (l & 15)) * ROWSTRIDE + (l >> 4) * 16;
    uint32_t boff[4];
    {
        int grp = l >> 3, nof = (grp >> 1) * 8 + (l & 7), cof = (grp & 1) * 16;
        #pragma unroll
        for (int p = 0; p < 4; ++p)
            boff[p] = ASTAGE_BYTES + (warp_n * 64 + p * 16 + nof) * ROWSTRIDE + cof;
    }

    #pragma unroll
    for (int it = 0; it < 2; ++it) {
        uint32_t so = sbase + it * STAGE_BYTES;
        const char* sa = srcA + it * 64;
        const char* sb = srcB + it * 64;
        CP16(so + dA, sa); CP16(so + dA + 16, sa + 16);
        CP16(so + dB, sb); CP16(so + dB + 16, sb + 16);
        CP_COMMIT();
    }

    float d[2][8][4];
    #pragma unroll
    for (int m = 0; m < 2; ++m)
        #pragma unroll
        for (int n = 0; n < 8; ++n)
            #pragma unroll
            for (int q = 0; q < 4; ++q) d[m][n][q] = 0.f;

    for (int it = 0; it < NITER; ++it) {
        if (it == NITER - 1) asm volatile("cp.async.wait_group 0;" ::: "memory");
        else                 asm volatile("cp.async.wait_group 1;" ::: "memory");
        __syncthreads();
        uint32_t sb = sbase + (it % 3) * STAGE_BYTES;
        #pragma unroll
        for (int ks = 0; ks < 2; ++ks) {
            uint32_t a[2][4], bb[8][2];
            #pragma unroll
            for (int m = 0; m < 2; ++m) ldmx4(a[m], sb + aoff[m] + ks * 32);
            #pragma unroll
            for (int p = 0; p < 4; ++p) {
                uint32_t r[4];
                ldmx4(r, sb + boff[p] + ks * 32);
                bb[2*p][0] = r[0]; bb[2*p][1] = r[1];
                bb[2*p+1][0] = r[2]; bb[2*p+1][1] = r[3];
            }
            #pragma unroll
            for (int m = 0; m < 2; ++m)
                #pragma unroll
                for (int n = 0; n < 8; ++n) mma16816(d[m][n], a[m], bb[n]);
        }
        if (it + 2 < NITER) {
            uint32_t so = sbase + ((it + 2) % 3) * STAGE_BYTES;
            const char* sa = srcA + (it + 2) * 64;
            const char* sb2 = srcB + (it + 2) * 64;
            CP16(so + dA, sa); CP16(so + dA + 16, sa + 16);
            CP16(so + dB, sb2); CP16(so + dB + 16, sb2 + 16);
            CP_COMMIT();
        }
    }

    // ---- epilogue ----
    __syncthreads();
    float* spart  = reinterpret_cast<float*>(smem);          // [128][2] row partials
    float* stagef = reinterpret_cast<float*>(smem + 1024);   // [j:128][TSTRIDE] transpose stage

    float sqi[4];
    #pragma unroll
    for (int m = 0; m < 2; ++m)
        #pragma unroll
        for (int h = 0; h < 2; ++h)
            sqi[2*m+h] = g_sq[b * Sdim + by * BM + warp_m * 32 + m * 16 + h * 8 + (l >> 2)];
    float2 sqj[8];
    #pragma unroll
    for (int n = 0; n < 8; ++n)
        sqj[n] = *reinterpret_cast<const float2*>(
            &g_sq[b * Sdim + bx * BN + warp_n * 64 + n * 8 + 2 * (l & 3)]);

    float* ob = out + ((size_t)b * Sdim + by * BM) * Sdim + bx * BN;
    float rs[4] = {0.f, 0.f, 0.f, 0.f};
    #pragma unroll
    for (int m = 0; m < 2; ++m) {
        #pragma unroll
        for (int h = 0; h < 2; ++h) {
            int row = warp_m * 32 + m * 16 + h * 8 + (l >> 2);
            float bi = -0.0625f * sqi[2*m+h];
            float* orow = ob + (size_t)row * Sdim + warp_n * 64 + 2 * (l & 3);
            float acc = 0.f;
            #pragma unroll
            for (int n = 0; n < 8; ++n) {
                float p0 = __expf(fmaf(d[m][n][2*h],     0.125f, fmaf(sqj[n].x, -0.0625f, bi)));
                float p1 = __expf(fmaf(d[m][n][2*h + 1], 0.125f, fmaf(sqj[n].y, -0.0625f, bi)));
                acc += p0 + p1;
                *reinterpret_cast<float2*>(orow + n * 8) = make_float2(p0, p1);
                if (offdiag) {
                    int col = warp_n * 64 + n * 8 + 2 * (l & 3);
                    stagef[(col)     * TSTRIDE + row] = p0;
                    stagef[(col + 1) * TSTRIDE + row] = p1;
                }
            }
            rs[2*m+h] = acc;
        }
    }
    #pragma unroll
    for (int i = 0; i < 4; ++i) {
        rs[i] += __shfl_xor_sync(0xffffffffu, rs[i], 1);
        rs[i] += __shfl_xor_sync(0xffffffffu, rs[i], 2);
    }
    if ((l & 3) == 0) {
        #pragma unroll
        for (int m = 0; m < 2; ++m)
            #pragma unroll
            for (int h = 0; h < 2; ++h) {
                int row = warp_m * 32 + m * 16 + h * 8 + (l >> 2);
                spart[row * 2 + warp_n] = rs[2*m+h];
            }
    }
    __syncthreads();
    if (tid < BM)
        g_part[((size_t)b * Sdim + by * BM + tid) * NPART + bx] =
            spart[tid * 2] + spart[tid * 2 + 1];

    if (offdiag) {
        // column sums -> row partials for the bx block (tile-col index by)
        {
            int j = tid >> 1, base = (tid & 1) * 64;
            const float* sp = stagef + j * TSTRIDE + base;
            float s = 0.f;
            #pragma unroll 16
            for (int k = 0; k < 64; ++k) s += sp[k];
            s += __shfl_xor_sync(0xffffffffu, s, 1);
            if (!(tid & 1))
                g_part[((size_t)b * Sdim + bx * BN + j) * NPART + by] = s;
        }
        // mirrored (transposed) tile store, coalesced
        float* obT = out + ((size_t)b * Sdim + bx * BN) * Sdim + by * BM;
        const int jrow = tid >> 6;           // 4 rows per pass
        const int c    = 2 * (tid & 63);     // 2 cols per thread
        #pragma unroll 8
        for (int it2 = 0; it2 < 32; ++it2) {
            int j = it2 * 4 + jrow;
            float2 v = *reinterpret_cast<const float2*>(&stagef[j * TSTRIDE + c]);
            *reinterpret_cast<float2*>(&obT[(size_t)j * Sdim + c]) = v;
        }
    }
}

// ================= Kernel 3: normalize =================
__global__ __launch_bounds__(256) void norm_kernel(float* __restrict__ out) {
    int w = threadIdx.x >> 5, l = threadIdx.x & 31;
    size_t row = (size_t)blockIdx.x * 8 + w;
    float v = (l < NPART) ? g_part[row * NPART + l] : 0.f;
    #pragma unroll
    for (int o = 16; o; o >>= 1) v += __shfl_xor_sync(0xffffffffu, v, o);
    float inv = 1.0f / v;
    float4* o4 = reinterpret_cast<float4*>(out + row * Sdim);
    #pragma unroll 4
    for (int k = 0; k < Sdim / 4 / 32; ++k) {
        float4 t = o4[l + 32 * k];
        t.x *= inv; t.y *= inv; t.z *= inv; t.w *= inv;
        o4[l + 32 * k] = t;
    }
}

extern "C" void kernel_launch(void* const* d_in, const int* in_sizes, int n_in,
                              void* d_out, int out_size) {
    const float* x  = (const float*)d_in[0];
    float*       out = (float*)d_out;

    cudaFuncSetAttribute(gemm_kernel, cudaFuncAttributeMaxDynamicSharedMemorySize, SMEM_DYN);

    split_kernel<<<NBATCH * Sdim / 8, 256>>>(x);
    gemm_kernel<<<dim3(NTRI, 1, NBATCH), 256, SMEM_DYN>>>(out);
    norm_kernel<<<NBATCH * Sdim / 8, 256>>>(out);
}